// round 3
// baseline (speedup 1.0000x reference)
#include <cuda_runtime.h>
#include <cuda_fp16.h>

#define DIM 300
#define C 16
#define NPTS 1048576   // 2^20
#define PLANE (DIM * DIM)

// fp16 scratch, (pos, channel) layout. 32B per texel.
// o=0 -> (plane_yz, line_x), o=1 -> (plane_xz, line_y), o=2 -> (plane_xy, line_z)
// +16 halves of zero-initialized pad so the weight-0 "x0+1 / j0+1" read at the
// clamp boundary stays in bounds.
__device__ __align__(16) __half g_plane_h[3 * PLANE * C + 16];
__device__ __align__(16) __half g_line_h[3 * DIM * C + 16];

__global__ void transpose_kernel(const float* __restrict__ pxy,
                                 const float* __restrict__ pyz,
                                 const float* __restrict__ pxz,
                                 const float* __restrict__ lx,
                                 const float* __restrict__ ly,
                                 const float* __restrict__ lz) {
    int id = blockIdx.x * blockDim.x + threadIdx.x;
    if (id < 3 * PLANE) {
        int p = id / PLANE;
        int pos = id - p * PLANE;
        const float* src = (p == 0) ? pyz : (p == 1) ? pxz : pxy;
        union { __half2 h2[8]; uint4 u[2]; } pk;
#pragma unroll
        for (int c = 0; c < 8; c++) {
            float a = __ldg(&src[(2 * c) * PLANE + pos]);
            float b = __ldg(&src[(2 * c + 1) * PLANE + pos]);
            pk.h2[c] = __floats2half2_rn(a, b);
        }
        uint4* dst = reinterpret_cast<uint4*>(g_plane_h + (p * PLANE + pos) * C);
        dst[0] = pk.u[0];
        dst[1] = pk.u[1];
    } else if (id < 3 * PLANE + 3 * DIM) {
        int r = id - 3 * PLANE;
        int p = r / DIM;
        int pos = r - p * DIM;
        const float* src = (p == 0) ? lx : (p == 1) ? ly : lz;
        union { __half2 h2[8]; uint4 u[2]; } pk;
#pragma unroll
        for (int c = 0; c < 8; c++) {
            float a = __ldg(&src[(2 * c) * DIM + pos]);
            float b = __ldg(&src[(2 * c + 1) * DIM + pos]);
            pk.h2[c] = __floats2half2_rn(a, b);
        }
        uint4* dst = reinterpret_cast<uint4*>(g_line_h + (p * DIM + pos) * C);
        dst[0] = pk.u[0];
        dst[1] = pk.u[1];
    }
}

__device__ __forceinline__ void unpack8(uint4 v, float2 f[4]) {
    f[0] = __half22float2(*reinterpret_cast<__half2*>(&v.x));
    f[1] = __half22float2(*reinterpret_cast<__half2*>(&v.y));
    f[2] = __half22float2(*reinterpret_cast<__half2*>(&v.z));
    f[3] = __half22float2(*reinterpret_cast<__half2*>(&v.w));
}

// 4 threads per (o, n). Thread q loads 16B of the 64B texel-pair row:
//   q=0: x0 ch0-7   q=1: x0 ch8-15   q=2: x0+1 ch0-7   q=3: x0+1 ch8-15
// Each computes its wx-weighted partial; shfl.xor(2)-add yields the full
// bilinear value. Same structure for the line taps (j0, j0+1).
__global__ void __launch_bounds__(256) sample_kernel(
    const float2* __restrict__ coords_plane,   // (3, N) float2
    const float2* __restrict__ coords_line,    // (3, N) float2
    float4* __restrict__ out)                  // (3, N, 4) float4
{
    int idx = blockIdx.x * blockDim.x + threadIdx.x;   // < 3 * N * 4
    int q = idx & 3;
    int t = idx >> 2;           // (o, n)
    int o = t >> 20;
    int n = t & (NPTS - 1);

    int po = (o == 0) ? 1 : (o == 1) ? 2 : 0;

    float2 pc = __ldg(&coords_plane[po * NPTS + n]);
    float2 lc = __ldg(&coords_line[o * NPTS + n]);

    const float S = 0.5f * (DIM - 1);

    // ---- plane bilinear ----
    float ix = (pc.x + 1.0f) * S;
    float iy = (pc.y + 1.0f) * S;
    float fx = floorf(ix), fy = floorf(iy);
    float wx = ix - fx, wy = iy - fy;
    int x0 = min(max((int)fx, 0), DIM - 1);
    int y0 = min(max((int)fy, 0), DIM - 1);
    int y1 = min(y0 + 1, DIM - 1);

    const __half* P = g_plane_h + o * (PLANE * C);
    uint4 r0 = *(reinterpret_cast<const uint4*>(P + (y0 * DIM + x0) * C) + q);
    uint4 r1 = *(reinterpret_cast<const uint4*>(P + (y1 * DIM + x0) * C) + q);

    float wq  = (q < 2) ? (1.0f - wx) : wx;
    float omwy = 1.0f - wy;

    float2 a[4], b[4];
    unpack8(r0, a);
    unpack8(r1, b);

    float pm[8];
#pragma unroll
    for (int i = 0; i < 4; i++) {
        pm[2 * i]     = (a[i].x * omwy + b[i].x * wy) * wq;
        pm[2 * i + 1] = (a[i].y * omwy + b[i].y * wy) * wq;
    }
#pragma unroll
    for (int c = 0; c < 8; c++)
        pm[c] += __shfl_xor_sync(0xffffffffu, pm[c], 2);

    // ---- line linear (only y coordinate matters; W==1) ----
    float iyl = (lc.y + 1.0f) * S;
    float fl = floorf(iyl);
    float wl = iyl - fl;
    int j0 = min(max((int)fl, 0), DIM - 1);

    const __half* L = g_line_h + o * (DIM * C);
    uint4 lr = *(reinterpret_cast<const uint4*>(L + j0 * C) + q);

    float lw = (q < 2) ? (1.0f - wl) : wl;
    float2 lf[4];
    unpack8(lr, lf);

    float lm[8];
#pragma unroll
    for (int i = 0; i < 4; i++) {
        lm[2 * i]     = lf[i].x * lw;
        lm[2 * i + 1] = lf[i].y * lw;
    }
#pragma unroll
    for (int c = 0; c < 8; c++)
        lm[c] += __shfl_xor_sync(0xffffffffu, lm[c], 2);

    // ---- product + store ----
    // thread q holds global channels (q&1)*8 .. +8 (duplicated across q, q^2).
    // q=0 writes ch0-3, q=2 writes ch4-7, q=1 writes ch8-11, q=3 writes ch12-15.
    int cl = (q >> 1) * 4;                  // local channel offset inside held 8
    int quarter = ((q & 1) << 1) | (q >> 1);
    float4 r;
    r.x = pm[cl]     * lm[cl];
    r.y = pm[cl + 1] * lm[cl + 1];
    r.z = pm[cl + 2] * lm[cl + 2];
    r.w = pm[cl + 3] * lm[cl + 3];
    out[t * 4 + quarter] = r;
}

extern "C" void kernel_launch(void* const* d_in, const int* in_sizes, int n_in,
                              void* d_out, int out_size) {
    const float* coords_plane = (const float*)d_in[0];
    const float* coords_line  = (const float*)d_in[1];
    const float* plane_xy     = (const float*)d_in[2];
    const float* plane_yz     = (const float*)d_in[3];
    const float* plane_xz     = (const float*)d_in[4];
    const float* line_x       = (const float*)d_in[5];
    const float* line_y       = (const float*)d_in[6];
    const float* line_z       = (const float*)d_in[7];
    float* out = (float*)d_out;

    {
        int total = 3 * PLANE + 3 * DIM;
        int block = 256;
        int grid = (total + block - 1) / block;
        transpose_kernel<<<grid, block>>>(plane_xy, plane_yz, plane_xz,
                                          line_x, line_y, line_z);
    }
    {
        long long total = 3LL * NPTS * 4;
        int block = 256;
        int grid = (int)(total / block);
        sample_kernel<<<grid, block>>>(
            reinterpret_cast<const float2*>(coords_plane),
            reinterpret_cast<const float2*>(coords_line),
            reinterpret_cast<float4*>(out));
    }
}

// round 4
// speedup vs baseline: 1.2056x; 1.2056x over previous
#include <cuda_runtime.h>
#include <cuda_fp16.h>

#define DIM 300
#define C 16
#define NPTS 1048576   // 2^20
#define PLANE (DIM * DIM)

// Pair-interleaved fp16 scratch.
// Plane block (o, y, x): 32 halves = 16 channels of __half2{ v[y][x], v[y][min(x+1,DIM-1)] }.
// Line  block (o, j):    32 halves = 16 channels of __half2{ v[j],    v[min(j+1,DIM-1)] }.
// o=0 -> (plane_yz, line_x), o=1 -> (plane_xz, line_y), o=2 -> (plane_xy, line_z)
__device__ __align__(16) __half g_plane_p[3 * PLANE * 2 * C];   // 17.28 MB
__device__ __align__(16) __half g_line_p[3 * DIM * 2 * C];      // 57.6 KB

__global__ void transpose_kernel(const float* __restrict__ pxy,
                                 const float* __restrict__ pyz,
                                 const float* __restrict__ pxz,
                                 const float* __restrict__ lx,
                                 const float* __restrict__ ly,
                                 const float* __restrict__ lz) {
    int id = blockIdx.x * blockDim.x + threadIdx.x;
    if (id < 3 * PLANE) {
        int p = id / PLANE;
        int pos = id - p * PLANE;       // y*DIM + x
        int x = pos % DIM;
        int dx = (x < DIM - 1) ? 1 : 0; // clamped neighbor offset
        const float* src = (p == 0) ? pyz : (p == 1) ? pxz : pxy;
        union { __half2 h2[16]; uint4 u[4]; } pk;
#pragma unroll
        for (int c = 0; c < C; c++) {
            float a = __ldg(&src[c * PLANE + pos]);
            float b = __ldg(&src[c * PLANE + pos + dx]);
            pk.h2[c] = __floats2half2_rn(a, b);
        }
        uint4* dst = reinterpret_cast<uint4*>(g_plane_p + (size_t)(p * PLANE + pos) * 2 * C);
#pragma unroll
        for (int j = 0; j < 4; j++) dst[j] = pk.u[j];
    } else if (id < 3 * PLANE + 3 * DIM) {
        int r = id - 3 * PLANE;
        int p = r / DIM;
        int pos = r - p * DIM;
        int dx = (pos < DIM - 1) ? 1 : 0;
        const float* src = (p == 0) ? lx : (p == 1) ? ly : lz;
        union { __half2 h2[16]; uint4 u[4]; } pk;
#pragma unroll
        for (int c = 0; c < C; c++) {
            float a = __ldg(&src[c * DIM + pos]);
            float b = __ldg(&src[c * DIM + pos + dx]);
            pk.h2[c] = __floats2half2_rn(a, b);
        }
        uint4* dst = reinterpret_cast<uint4*>(g_line_p + (size_t)(p * DIM + pos) * 2 * C);
#pragma unroll
        for (int j = 0; j < 4; j++) dst[j] = pk.u[j];
    }
}

// 4 threads per (o, n); thread q owns channels 4q..4q+3 end-to-end (no shuffles).
// Per thread: 2 plane-row uint4 loads (each = both x-corners of its channels),
// 1 line uint4 load (both taps), fp32 lerp math, one float4 store.
__global__ void __launch_bounds__(256) sample_kernel(
    const float2* __restrict__ coords_plane,   // (3, N)
    const float2* __restrict__ coords_line,    // (3, N)
    float4* __restrict__ out)                  // (3, N, 4) float4
{
    int idx = blockIdx.x * blockDim.x + threadIdx.x;   // < 3 * N * 4
    int q = idx & 3;
    int t = idx >> 2;
    int o = t >> 20;
    int n = t & (NPTS - 1);

    int po = (o == 0) ? 1 : (o == 1) ? 2 : 0;

    float2 pc = __ldg(&coords_plane[po * NPTS + n]);
    float2 lc = __ldg(&coords_line[o * NPTS + n]);

    const float S = 0.5f * (DIM - 1);

    // plane indices/weights (ix >= 0 always; clamps are safety + edge wx=0 case)
    float ix = (pc.x + 1.0f) * S;
    float iy = (pc.y + 1.0f) * S;
    float fx = floorf(ix), fy = floorf(iy);
    float wx = ix - fx, wy = iy - fy;
    int x0 = min(max((int)fx, 0), DIM - 1);
    int y0 = min(max((int)fy, 0), DIM - 1);
    int y1 = min(y0 + 1, DIM - 1);

    const uint4* P = reinterpret_cast<const uint4*>(g_plane_p) + (size_t)o * PLANE * 4;
    uint4 r0 = P[(y0 * DIM + x0) * 4 + q];
    uint4 r1 = P[(y1 * DIM + x0) * 4 + q];

    // line index/weight
    float iyl = (lc.y + 1.0f) * S;
    float fl = floorf(iyl);
    float wl = iyl - fl;
    int j0 = min(max((int)fl, 0), DIM - 1);

    const uint4* L = reinterpret_cast<const uint4*>(g_line_p) + (size_t)o * DIM * 4;
    uint4 lr = L[j0 * 4 + q];

    const __half2* h0 = reinterpret_cast<const __half2*>(&r0);
    const __half2* h1 = reinterpret_cast<const __half2*>(&r1);
    const __half2* hl = reinterpret_cast<const __half2*>(&lr);

    float res[4];
#pragma unroll
    for (int i = 0; i < 4; i++) {
        float2 f0 = __half22float2(h0[i]);   // (v[y0][x0], v[y0][x1])
        float2 f1 = __half22float2(h1[i]);   // (v[y1][x0], v[y1][x1])
        float2 fl2 = __half22float2(hl[i]);  // (l[j0], l[j1])
        float vx0 = fmaf(wx, f0.y - f0.x, f0.x);
        float vx1 = fmaf(wx, f1.y - f1.x, f1.x);
        float v   = fmaf(wy, vx1 - vx0, vx0);
        float lv  = fmaf(wl, fl2.y - fl2.x, fl2.x);
        res[i] = v * lv;
    }

    out[idx] = make_float4(res[0], res[1], res[2], res[3]);
}

extern "C" void kernel_launch(void* const* d_in, const int* in_sizes, int n_in,
                              void* d_out, int out_size) {
    const float* coords_plane = (const float*)d_in[0];
    const float* coords_line  = (const float*)d_in[1];
    const float* plane_xy     = (const float*)d_in[2];
    const float* plane_yz     = (const float*)d_in[3];
    const float* plane_xz     = (const float*)d_in[4];
    const float* line_x       = (const float*)d_in[5];
    const float* line_y       = (const float*)d_in[6];
    const float* line_z       = (const float*)d_in[7];
    float* out = (float*)d_out;

    {
        int total = 3 * PLANE + 3 * DIM;
        int block = 256;
        int grid = (total + block - 1) / block;
        transpose_kernel<<<grid, block>>>(plane_xy, plane_yz, plane_xz,
                                          line_x, line_y, line_z);
    }
    {
        long long total = 3LL * NPTS * 4;
        int block = 256;
        int grid = (int)(total / block);
        sample_kernel<<<grid, block>>>(
            reinterpret_cast<const float2*>(coords_plane),
            reinterpret_cast<const float2*>(coords_line),
            reinterpret_cast<float4*>(out));
    }
}

// round 5
// speedup vs baseline: 1.2118x; 1.0051x over previous
#include <cuda_runtime.h>
#include <cuda_fp16.h>

#define DIM 300
#define C 16
#define NPTS 1048576   // 2^20
#define PLANE (DIM * DIM)

// Pair-interleaved fp16 scratch (x-neighbor pre-clamped at build time).
// Plane block (o, y, x): 32 halves = 16 ch of __half2{ v[y][x], v[y][min(x+1,DIM-1)] }.
// Line  block (o, j):    32 halves = 16 ch of __half2{ v[j],    v[min(j+1,DIM-1)] }.
// o=0 -> (plane_yz, line_x), o=1 -> (plane_xz, line_y), o=2 -> (plane_xy, line_z)
__device__ __align__(128) __half g_plane_p[3 * PLANE * 2 * C];   // 17.28 MB
__device__ __align__(128) __half g_line_p[3 * DIM * 2 * C];      // 57.6 KB

__global__ void transpose_kernel(const float* __restrict__ pxy,
                                 const float* __restrict__ pyz,
                                 const float* __restrict__ pxz,
                                 const float* __restrict__ lx,
                                 const float* __restrict__ ly,
                                 const float* __restrict__ lz) {
    int id = blockIdx.x * blockDim.x + threadIdx.x;
    if (id < 3 * PLANE) {
        int p = id / PLANE;
        int pos = id - p * PLANE;       // y*DIM + x
        int x = pos % DIM;
        int dx = (x < DIM - 1) ? 1 : 0;
        const float* src = (p == 0) ? pyz : (p == 1) ? pxz : pxy;
        union { __half2 h2[16]; uint4 u[4]; } pk;
#pragma unroll
        for (int c = 0; c < C; c++) {
            float a = __ldg(&src[c * PLANE + pos]);
            float b = __ldg(&src[c * PLANE + pos + dx]);
            pk.h2[c] = __floats2half2_rn(a, b);
        }
        uint4* dst = reinterpret_cast<uint4*>(g_plane_p + (size_t)(p * PLANE + pos) * 2 * C);
#pragma unroll
        for (int j = 0; j < 4; j++) dst[j] = pk.u[j];
    } else if (id < 3 * PLANE + 3 * DIM) {
        int r = id - 3 * PLANE;
        int p = r / DIM;
        int pos = r - p * DIM;
        int dx = (pos < DIM - 1) ? 1 : 0;
        const float* src = (p == 0) ? lx : (p == 1) ? ly : lz;
        union { __half2 h2[16]; uint4 u[4]; } pk;
#pragma unroll
        for (int c = 0; c < C; c++) {
            float a = __ldg(&src[c * DIM + pos]);
            float b = __ldg(&src[c * DIM + pos + dx]);
            pk.h2[c] = __floats2half2_rn(a, b);
        }
        uint4* dst = reinterpret_cast<uint4*>(g_line_p + (size_t)(p * DIM + pos) * 2 * C);
#pragma unroll
        for (int j = 0; j < 4; j++) dst[j] = pk.u[j];
    }
}

// One quarter-task: (o, n, q) -> bilinear * line for channels 4q..4q+3.
// No clamps: coords are strictly in [-1, 1), so x0,y0,j0 in [0, DIM-2] ... [0, DIM-1]
// and y0+1 <= DIM-1; the x/j "+1" neighbor is pre-clamped inside the scratch block.
__device__ __forceinline__ void do_task(int id,
                                        const float2* __restrict__ coords_plane,
                                        const float2* __restrict__ coords_line,
                                        float4* __restrict__ out) {
    int q = id & 3;
    int t = id >> 2;
    int o = t >> 20;
    int n = t & (NPTS - 1);
    int po = (o == 2) ? 0 : o + 1;

    float2 pc = __ldg(&coords_plane[po * NPTS + n]);
    float2 lc = __ldg(&coords_line[o * NPTS + n]);

    const float S = 0.5f * (DIM - 1);

    float ix = (pc.x + 1.0f) * S;
    float iy = (pc.y + 1.0f) * S;
    int x0 = (int)ix;                 // trunc == floor (ix >= 0)
    int y0 = (int)iy;
    float wx = ix - (float)x0;
    float wy = iy - (float)y0;

    const uint4* P = reinterpret_cast<const uint4*>(g_plane_p) + (size_t)o * PLANE * 4;
    int pbase = (y0 * DIM + x0) * 4 + q;
    uint4 r0 = P[pbase];
    uint4 r1 = P[pbase + DIM * 4];    // row y0+1 (valid: y0 <= DIM-2)

    float iyl = (lc.y + 1.0f) * S;
    int j0 = (int)iyl;
    float wl = iyl - (float)j0;

    const uint4* L = reinterpret_cast<const uint4*>(g_line_p) + (size_t)o * DIM * 4;
    uint4 lr = L[j0 * 4 + q];

    const __half2* h0 = reinterpret_cast<const __half2*>(&r0);
    const __half2* h1 = reinterpret_cast<const __half2*>(&r1);
    const __half2* hl = reinterpret_cast<const __half2*>(&lr);

    float res[4];
#pragma unroll
    for (int i = 0; i < 4; i++) {
        float2 f0 = __half22float2(h0[i]);   // (v[y0][x0], v[y0][x1])
        float2 f1 = __half22float2(h1[i]);   // (v[y1][x0], v[y1][x1])
        float2 fl2 = __half22float2(hl[i]);  // (l[j0], l[j1])
        float vx0 = fmaf(wx, f0.y - f0.x, f0.x);
        float vx1 = fmaf(wx, f1.y - f1.x, f1.x);
        float v   = fmaf(wy, vx1 - vx0, vx0);
        float lv  = fmaf(wl, fl2.y - fl2.x, fl2.x);
        res[i] = v * lv;
    }

    __stcs(&out[id], make_float4(res[0], res[1], res[2], res[3]));
}

// 2 quarter-tasks per thread (ids base and base + 3N/2*4); both halves are
// warp-uniform in o. 8 independent loads in flight per thread.
__global__ void __launch_bounds__(256, 6) sample_kernel(
    const float2* __restrict__ coords_plane,   // (3, N)
    const float2* __restrict__ coords_line,    // (3, N)
    float4* __restrict__ out)                  // (3, N, 4) float4
{
    int base = blockIdx.x * blockDim.x + threadIdx.x;   // < 3*N*2
    do_task(base, coords_plane, coords_line, out);
    do_task(base + 3 * NPTS * 2, coords_plane, coords_line, out);
}

extern "C" void kernel_launch(void* const* d_in, const int* in_sizes, int n_in,
                              void* d_out, int out_size) {
    const float* coords_plane = (const float*)d_in[0];
    const float* coords_line  = (const float*)d_in[1];
    const float* plane_xy     = (const float*)d_in[2];
    const float* plane_yz     = (const float*)d_in[3];
    const float* plane_xz     = (const float*)d_in[4];
    const float* line_x       = (const float*)d_in[5];
    const float* line_y       = (const float*)d_in[6];
    const float* line_z       = (const float*)d_in[7];
    float* out = (float*)d_out;

    {
        int total = 3 * PLANE + 3 * DIM;
        int block = 256;
        int grid = (total + block - 1) / block;
        transpose_kernel<<<grid, block>>>(plane_xy, plane_yz, plane_xz,
                                          line_x, line_y, line_z);
    }
    {
        int threads_total = 3 * NPTS * 2;      // 6,291,456
        int block = 256;
        int grid = threads_total / block;      // 24576
        sample_kernel<<<grid, block>>>(
            reinterpret_cast<const float2*>(coords_plane),
            reinterpret_cast<const float2*>(coords_line),
            reinterpret_cast<float4*>(out));
    }
}

// round 7
// speedup vs baseline: 1.3647x; 1.1262x over previous
#include <cuda_runtime.h>
#include <cuda_fp16.h>

#define DIM 300
#define C 16
#define NPTS 1048576   // 2^20
#define PLANE (DIM * DIM)

// Pair-interleaved fp16 scratch (x-neighbor pre-clamped at build time).
// Plane block (o, y, x): 32 halves = 16 ch of __half2{ v[y][x], v[y][min(x+1,DIM-1)] }.
// Line  block (o, j):    32 halves = 16 ch of __half2{ v[j],    v[min(j+1,DIM-1)] }.
// o=0 -> (plane_yz, line_x), o=1 -> (plane_xz, line_y), o=2 -> (plane_xy, line_z)
__device__ __align__(128) __half g_plane_p[3 * PLANE * 2 * C];   // 17.28 MB
__device__ __align__(128) __half g_line_p[3 * DIM * 2 * C];      // 57.6 KB

__global__ void transpose_kernel(const float* __restrict__ pxy,
                                 const float* __restrict__ pyz,
                                 const float* __restrict__ pxz,
                                 const float* __restrict__ lx,
                                 const float* __restrict__ ly,
                                 const float* __restrict__ lz) {
    int id = blockIdx.x * blockDim.x + threadIdx.x;
    if (id < 3 * PLANE) {
        int p = id / PLANE;
        int pos = id - p * PLANE;       // y*DIM + x
        int x = pos % DIM;
        int dx = (x < DIM - 1) ? 1 : 0;
        const float* src = (p == 0) ? pyz : (p == 1) ? pxz : pxy;
        union { __half2 h2[16]; uint4 u[4]; } pk;
#pragma unroll
        for (int c = 0; c < C; c++) {
            float a = __ldg(&src[c * PLANE + pos]);
            float b = __ldg(&src[c * PLANE + pos + dx]);
            pk.h2[c] = __floats2half2_rn(a, b);
        }
        uint4* dst = reinterpret_cast<uint4*>(g_plane_p + (size_t)(p * PLANE + pos) * 2 * C);
#pragma unroll
        for (int j = 0; j < 4; j++) dst[j] = pk.u[j];
    } else if (id < 3 * PLANE + 3 * DIM) {
        int r = id - 3 * PLANE;
        int p = r / DIM;
        int pos = r - p * DIM;
        int dx = (pos < DIM - 1) ? 1 : 0;
        const float* src = (p == 0) ? lx : (p == 1) ? ly : lz;
        union { __half2 h2[16]; uint4 u[4]; } pk;
#pragma unroll
        for (int c = 0; c < C; c++) {
            float a = __ldg(&src[c * DIM + pos]);
            float b = __ldg(&src[c * DIM + pos + dx]);
            pk.h2[c] = __floats2half2_rn(a, b);
        }
        uint4* dst = reinterpret_cast<uint4*>(g_line_p + (size_t)(p * DIM + pos) * 2 * C);
#pragma unroll
        for (int j = 0; j < 4; j++) dst[j] = pk.u[j];
    }
}

struct Task {
    int pbase;      // plane uint4 index (incl. q)
    int lbase;      // line  uint4 index (incl. q)
    int o;
    float wx, wy, wl;
};

__device__ __forceinline__ Task decode(int id,
                                       const float2* __restrict__ coords_plane,
                                       const float2* __restrict__ coords_line) {
    Task tk;
    int q = id & 3;
    int t = id >> 2;
    tk.o = t >> 20;
    int n = t & (NPTS - 1);
    int po = (tk.o == 2) ? 0 : tk.o + 1;

    float2 pc = __ldg(&coords_plane[po * NPTS + n]);
    float2 lc = __ldg(&coords_line[tk.o * NPTS + n]);

    const float S = 0.5f * (DIM - 1);
    float ix = (pc.x + 1.0f) * S;
    float iy = (pc.y + 1.0f) * S;
    int x0 = (int)ix;                 // trunc == floor (coords in [-1,1) => ix >= 0)
    int y0 = (int)iy;
    tk.wx = ix - (float)x0;
    tk.wy = iy - (float)y0;
    tk.pbase = (y0 * DIM + x0) * 4 + q;

    float iyl = (lc.y + 1.0f) * S;
    int j0 = (int)iyl;
    tk.wl = iyl - (float)j0;
    tk.lbase = j0 * 4 + q;
    return tk;
}

__device__ __forceinline__ float4 combine(uint4 r0, uint4 r1, uint4 lr,
                                          float wx, float wy, float wl) {
    const __half2* h0 = reinterpret_cast<const __half2*>(&r0);
    const __half2* h1 = reinterpret_cast<const __half2*>(&r1);
    const __half2* hl = reinterpret_cast<const __half2*>(&lr);
    float res[4];
#pragma unroll
    for (int i = 0; i < 4; i++) {
        float2 f0 = __half22float2(h0[i]);   // (v[y0][x0], v[y0][x1])
        float2 f1 = __half22float2(h1[i]);   // (v[y1][x0], v[y1][x1])
        float2 fl2 = __half22float2(hl[i]);  // (l[j0], l[j1])
        float vx0 = fmaf(wx, f0.y - f0.x, f0.x);
        float vx1 = fmaf(wx, f1.y - f1.x, f1.x);
        float v   = fmaf(wy, vx1 - vx0, vx0);
        float lv  = fmaf(wl, fl2.y - fl2.x, fl2.x);
        res[i] = v * lv;
    }
    return make_float4(res[0], res[1], res[2], res[3]);
}

// 2 tasks per thread, loads of BOTH tasks issued before any unpack/FMA.
// Plane loads use .cg (L1 bypass: zero reuse in 17MB random-access scratch,
// keeps L1 for the hot 19KB line tables + coords). 6 texel loads in flight.
__global__ void __launch_bounds__(128, 9) sample_kernel(
    const float2* __restrict__ coords_plane,   // (3, N)
    const float2* __restrict__ coords_line,    // (3, N)
    float4* __restrict__ out)                  // (3, N, 4) float4
{
    int base = blockIdx.x * blockDim.x + threadIdx.x;   // < 3*N*2
    const int HALF = 3 * NPTS * 2;                      // id stride between tasks

    Task A = decode(base, coords_plane, coords_line);
    Task B = decode(base + HALF, coords_plane, coords_line);

    const uint4* PA = reinterpret_cast<const uint4*>(g_plane_p) + (size_t)A.o * PLANE * 4;
    const uint4* PB = reinterpret_cast<const uint4*>(g_plane_p) + (size_t)B.o * PLANE * 4;
    const uint4* LA = reinterpret_cast<const uint4*>(g_line_p) + (size_t)A.o * DIM * 4;
    const uint4* LB = reinterpret_cast<const uint4*>(g_line_p) + (size_t)B.o * DIM * 4;

    // ---- issue all 6 texel loads ----
    uint4 a0 = __ldcg(&PA[A.pbase]);
    uint4 a1 = __ldcg(&PA[A.pbase + DIM * 4]);
    uint4 b0 = __ldcg(&PB[B.pbase]);
    uint4 b1 = __ldcg(&PB[B.pbase + DIM * 4]);
    uint4 la = LA[A.lbase];
    uint4 lb = LB[B.lbase];

    // ---- compute + store ----
    __stcs(&out[base], combine(a0, a1, la, A.wx, A.wy, A.wl));
    __stcs(&out[base + HALF], combine(b0, b1, lb, B.wx, B.wy, B.wl));
}

extern "C" void kernel_launch(void* const* d_in, const int* in_sizes, int n_in,
                              void* d_out, int out_size) {
    const float* coords_plane = (const float*)d_in[0];
    const float* coords_line  = (const float*)d_in[1];
    const float* plane_xy     = (const float*)d_in[2];
    const float* plane_yz     = (const float*)d_in[3];
    const float* plane_xz     = (const float*)d_in[4];
    const float* line_x       = (const float*)d_in[5];
    const float* line_y       = (const float*)d_in[6];
    const float* line_z       = (const float*)d_in[7];
    float* out = (float*)d_out;

    {
        int total = 3 * PLANE + 3 * DIM;
        int block = 256;
        int grid = (total + block - 1) / block;
        transpose_kernel<<<grid, block>>>(plane_xy, plane_yz, plane_xz,
                                          line_x, line_y, line_z);
    }
    {
        int threads_total = 3 * NPTS * 2;      // 6,291,456
        int block = 128;
        int grid = threads_total / block;      // 49152
        sample_kernel<<<grid, block>>>(
            reinterpret_cast<const float2*>(coords_plane),
            reinterpret_cast<const float2*>(coords_line),
            reinterpret_cast<float4*>(out));
    }
}